// round 4
// baseline (speedup 1.0000x reference)
#include <cuda_runtime.h>
#include <cstdint>

#define NB 64
#define NO 10
#define NI 8000
#define ND 16
#define NE 8

#define ITILE 2
#define NTHR 1024
#define NSTAGES (NI / ITILE)   // 4000 stages of 2 i's
#define NBLK 296               // persistent blocks, 2 waves of 148

// Scratch (no allocation allowed). g_s zeroed by the fused squash each pass,
// g_ticket reset by the last block -> graph replays are deterministic.
__device__ float g_s[NB * NO * ND] = {};
__device__ float g_v[NB * NO * ND] = {};
__device__ float g_vsum[NB * NO * ND] = {};
__device__ unsigned int g_ticket = 0;

// ---- f32x2 packed math (sm_10x; ptxas won't auto-fuse, must be PTX) ----
__device__ __forceinline__ unsigned long long f2mul(unsigned long long a, unsigned long long b) {
    unsigned long long d;
    asm("mul.rn.f32x2 %0, %1, %2;" : "=l"(d) : "l"(a), "l"(b));
    return d;
}
__device__ __forceinline__ unsigned long long f2fma(unsigned long long a, unsigned long long b, unsigned long long c) {
    unsigned long long d;
    asm("fma.rn.f32x2 %0, %1, %2, %3;" : "=l"(d) : "l"(a), "l"(b), "l"(c));
    return d;
}
__device__ __forceinline__ float f2hadd(unsigned long long a) {
    float lo, hi;
    asm("mov.b64 {%0, %1}, %2;" : "=f"(lo), "=f"(hi) : "l"(a));
    return lo + hi;
}

// ---- cp.async (LDGSTS) helpers ----
__device__ __forceinline__ void cp16(uint32_t dst, const void* src) {
    asm volatile("cp.async.ca.shared.global [%0], [%1], 16;" :: "r"(dst), "l"(src));
}
__device__ __forceinline__ void cp_commit() { asm volatile("cp.async.commit_group;"); }
template <int N>
__device__ __forceinline__ void cp_wait() { asm volatile("cp.async.wait_group %0;" :: "n"(N)); }
__device__ __forceinline__ uint32_t sptr(const void* p) {
    return (uint32_t)__cvta_generic_to_shared(p);
}

// One fused pass: recompute u_hat tile-by-tile (double-buffered cp.async
// staging), route, accumulate s in regs, flush with atomics; LAST block
// performs squash (fused epilogue).
// Thread layout: lane = d (16), grp = batch (64 groups, 1 batch per thread).
template <int ITER>
__global__ void __launch_bounds__(NTHR, 1)
pass_kernel(const float* __restrict__ xg, const float* __restrict__ Wg,
            float* __restrict__ out)
{
    __shared__ float4 shW[2][ITILE * NO * 32];  // 2 x 10 KB, (j,o): idx = e4*16 + d
    __shared__ float4 shx[2][ITILE * NB * 2];   // 2 x 4 KB

    const int tid  = threadIdx.x;
    const int lane = tid & 15;   // d
    const int b    = tid >> 4;   // batch 0..63

    const bool s8 = (lane & 8) != 0;
    const bool s4 = (lane & 4) != 0;
    const bool s2 = (lane & 2) != 0;
    const bool s1 = (lane & 1) != 0;
    // lane g holds a[o(g)]; valid (non-duplicate) lanes for softmax denom:
    const bool validLane = (!s1) || (!s2 && !s4);

    float vr[NO];
    if (ITER >= 1) {
        const float* vin = (ITER == 1) ? g_v : g_vsum;
        #pragma unroll
        for (int o = 0; o < NO; o++) vr[o] = vin[(b * NO + o) * ND + lane];
    }

    unsigned long long accp[NO];  // ITER 0: packed accumulators
    float acc[NO];
    #pragma unroll
    for (int o = 0; o < NO; o++) { accp[o] = 0ull; acc[o] = 0.f; }

    const float4* Wf4 = (const float4*)Wg;
    const float4* xf4 = (const float4*)xg;

    // staging: one cp.async(16B) per thread per stage (896 items, 1024 thr)
    auto stage_load = [&](int buf, int st) {
        const int i0 = st * ITILE;
        if (tid < ITILE * NO * 32) {                     // 640 W float4s
            int j  = tid / (NO * 32);
            int r  = tid - j * (NO * 32);
            int o  = r >> 5;
            int qg = r & 31;                       // global f4 index = d*2 + e4
            int qs = ((qg & 1) << 4) | (qg >> 1);  // shared index = e4*16 + d
            cp16(sptr(&shW[buf][(j * NO + o) * 32 + qs]),
                 &Wf4[(o * NI + i0 + j) * 32 + qg]);
        } else if (tid < ITILE * NO * 32 + ITILE * NB * 2) {  // 256 x float4s
            int v = tid - ITILE * NO * 32;
            int j = v >> 7;
            int r = v & 127;
            int bb = r >> 1;
            int q  = r & 1;
            cp16(sptr(&shx[buf][(j * NB + bb) * 2 + q]),
                 &xf4[((bb * NI + i0 + j) << 1) + q]);
        }
    };

    // prologue: stage this block's first tile
    stage_load(0, blockIdx.x);
    cp_commit();

    int parity = 0;
    for (int st = blockIdx.x; st < NSTAGES; st += NBLK) {
        const int nxt = st + NBLK;
        if (nxt < NSTAGES) {
            stage_load(parity ^ 1, nxt);
            cp_commit();
            cp_wait<1>();           // current stage's group complete
        } else {
            cp_wait<0>();
        }
        __syncthreads();

        const ulonglong2* shWc = reinterpret_cast<const ulonglong2*>(shW[parity]);
        const ulonglong2* shxc = reinterpret_cast<const ulonglong2*>(shx[parity]);

        #pragma unroll
        for (int j = 0; j < ITILE; j++) {
            ulonglong2 xa = shxc[(j * NB + b) * 2 + 0];  // (e0,e1),(e2,e3)
            ulonglong2 xb = shxc[(j * NB + b) * 2 + 1];  // (e4,e5),(e6,e7)

            if (ITER == 0) {
                #pragma unroll
                for (int o = 0; o < NO; o++) {
                    ulonglong2 wa = shWc[(j * NO + o) * 32 + lane];       // e0..3
                    ulonglong2 wb = shWc[(j * NO + o) * 32 + 16 + lane];  // e4..7
                    accp[o] = f2fma(wa.x, xa.x, accp[o]);
                    accp[o] = f2fma(wa.y, xa.y, accp[o]);
                    accp[o] = f2fma(wb.x, xb.x, accp[o]);
                    accp[o] = f2fma(wb.y, xb.y, accp[o]);
                }
            } else {
                float u[NO];
                #pragma unroll
                for (int o = 0; o < NO; o++) {
                    ulonglong2 wa = shWc[(j * NO + o) * 32 + lane];
                    ulonglong2 wb = shWc[(j * NO + o) * 32 + 16 + lane];
                    unsigned long long t = f2mul(wa.x, xa.x);
                    t = f2fma(wa.y, xa.y, t);
                    t = f2fma(wb.x, xb.x, t);
                    t = f2fma(wb.y, xb.y, t);
                    u[o] = f2hadd(t);
                }

                // pairing-tree reduction of p[o] = u[o]*vr[o] over 16 d-lanes
                float p[NO];
                #pragma unroll
                for (int o = 0; o < NO; o++) p[o] = u[o] * vr[o];

                float q[5];
                #pragma unroll
                for (int k = 0; k < 5; k++) {
                    float keep = s8 ? p[2 * k + 1] : p[2 * k];
                    float send = s8 ? p[2 * k] : p[2 * k + 1];
                    q[k] = keep + __shfl_xor_sync(0xffffffffu, send, 8, 16);
                }
                float r0, r1, r2;
                {
                    float keep = s4 ? q[1] : q[0];
                    float send = s4 ? q[0] : q[1];
                    r0 = keep + __shfl_xor_sync(0xffffffffu, send, 4, 16);
                }
                {
                    float keep = s4 ? q[3] : q[2];
                    float send = s4 ? q[2] : q[3];
                    r1 = keep + __shfl_xor_sync(0xffffffffu, send, 4, 16);
                }
                r2 = q[4] + __shfl_xor_sync(0xffffffffu, q[4], 4, 16);
                float t0, t1;
                {
                    float keep = s2 ? r1 : r0;
                    float send = s2 ? r0 : r1;
                    t0 = keep + __shfl_xor_sync(0xffffffffu, send, 2, 16);
                }
                t1 = r2 + __shfl_xor_sync(0xffffffffu, r2, 2, 16);
                float a;
                {
                    float keep = s1 ? t1 : t0;
                    float send = s1 ? t0 : t1;
                    a = keep + __shfl_xor_sync(0xffffffffu, send, 1, 16);
                }

                // distributed softmax (logits tiny -> no max subtraction)
                float e = __expf(a);
                float m = validLane ? e : 0.f;
                m += __shfl_xor_sync(0xffffffffu, m, 8, 16);
                m += __shfl_xor_sync(0xffffffffu, m, 4, 16);
                m += __shfl_xor_sync(0xffffffffu, m, 2, 16);
                m += __shfl_xor_sync(0xffffffffu, m, 1, 16);
                float c_self = __fdividef(e, m);

                // broadcast c[o] from its owner lane, accumulate
                // o -> lane: {0,8,4,12,2,10,6,14,1,9}
                acc[0] = fmaf(__shfl_sync(0xffffffffu, c_self, 0, 16),  u[0], acc[0]);
                acc[1] = fmaf(__shfl_sync(0xffffffffu, c_self, 8, 16),  u[1], acc[1]);
                acc[2] = fmaf(__shfl_sync(0xffffffffu, c_self, 4, 16),  u[2], acc[2]);
                acc[3] = fmaf(__shfl_sync(0xffffffffu, c_self, 12, 16), u[3], acc[3]);
                acc[4] = fmaf(__shfl_sync(0xffffffffu, c_self, 2, 16),  u[4], acc[4]);
                acc[5] = fmaf(__shfl_sync(0xffffffffu, c_self, 10, 16), u[5], acc[5]);
                acc[6] = fmaf(__shfl_sync(0xffffffffu, c_self, 6, 16),  u[6], acc[6]);
                acc[7] = fmaf(__shfl_sync(0xffffffffu, c_self, 14, 16), u[7], acc[7]);
                acc[8] = fmaf(__shfl_sync(0xffffffffu, c_self, 1, 16),  u[8], acc[8]);
                acc[9] = fmaf(__shfl_sync(0xffffffffu, c_self, 9, 16),  u[9], acc[9]);
            }
        }

        __syncthreads();  // compute done before next iter overwrites this buffer
        parity ^= 1;
    }

    if (ITER == 0) {
        #pragma unroll
        for (int o = 0; o < NO; o++) acc[o] = f2hadd(accp[o]);
    }
    #pragma unroll
    for (int o = 0; o < NO; o++)
        atomicAdd(&g_s[(b * NO + o) * ND + lane], acc[o]);

    // ---- fused squash: last block to finish does the epilogue ----
    __threadfence();
    __shared__ unsigned int lastFlag;
    if (tid == 0)
        lastFlag = (atomicAdd(&g_ticket, 1u) == (unsigned)(gridDim.x - 1)) ? 1u : 0u;
    __syncthreads();
    if (!lastFlag) return;
    __threadfence();  // acquire: all other blocks' atomics are visible

    const float prescale = (ITER == 0) ? 0.1f : 1.0f;
    #pragma unroll
    for (int k = 0; k < (NB * NO * ND) / NTHR; k++) {
        int idx = k * NTHR + tid;            // idx & 15 == lane (NTHR % 16 == 0)
        float val = g_s[idx] * prescale;
        g_s[idx] = 0.f;
        float n2 = val * val;
        n2 += __shfl_xor_sync(0xffffffffu, n2, 8, 16);
        n2 += __shfl_xor_sync(0xffffffffu, n2, 4, 16);
        n2 += __shfl_xor_sync(0xffffffffu, n2, 2, 16);
        n2 += __shfl_xor_sync(0xffffffffu, n2, 1, 16);
        float norm  = sqrtf(n2);
        float scale = n2 / ((1.f + n2) * (norm + 1e-8f));
        float v = scale * val;
        if (ITER == 0)      { g_v[idx] = v; g_vsum[idx] = v; }
        else if (ITER == 1) { g_v[idx] = v; g_vsum[idx] += v; }
        else                { out[idx] = v; }
    }
    if (tid == 0) g_ticket = 0;  // reset for next pass / next graph replay
}

extern "C" void kernel_launch(void* const* d_in, const int* in_sizes, int n_in,
                              void* d_out, int out_size)
{
    const float* x = (const float*)d_in[0];  // [64, 8000, 8]
    const float* W = (const float*)d_in[1];  // [10, 8000, 16, 8]
    float* out = (float*)d_out;              // [64, 10, 16]

    pass_kernel<0><<<NBLK, NTHR>>>(x, W, out);  // uniform c=0.1 (in prescale)
    pass_kernel<1><<<NBLK, NTHR>>>(x, W, out);  // c = softmax_o(u.v0)
    pass_kernel<2><<<NBLK, NTHR>>>(x, W, out);  // c = softmax_o(u.(v0+v1))
}

// round 5
// speedup vs baseline: 1.1673x; 1.1673x over previous
#include <cuda_runtime.h>
#include <cstdint>

#define NB 64
#define NO 10
#define NI 8000
#define ND 16
#define NE 8

#define ITILE 2
#define NTHR 512
#define NSTAGES (NI / ITILE)   // 4000 stages of 2 i's
#define NBLK 296               // 2 blocks/SM resident (persistent)

// Scratch (no allocation allowed). g_s zeroed by the fused squash each pass,
// g_ticket reset by the last block -> graph replays are deterministic.
__device__ float g_s[NB * NO * ND] = {};
__device__ float g_v[NB * NO * ND] = {};
__device__ float g_vsum[NB * NO * ND] = {};
__device__ unsigned int g_ticket = 0;

// ---- f32x2 packed math (sm_10x; ptxas won't auto-fuse, must be PTX) ----
__device__ __forceinline__ unsigned long long f2mul(unsigned long long a, unsigned long long b) {
    unsigned long long d;
    asm("mul.rn.f32x2 %0, %1, %2;" : "=l"(d) : "l"(a), "l"(b));
    return d;
}
__device__ __forceinline__ unsigned long long f2fma(unsigned long long a, unsigned long long b, unsigned long long c) {
    unsigned long long d;
    asm("fma.rn.f32x2 %0, %1, %2, %3;" : "=l"(d) : "l"(a), "l"(b), "l"(c));
    return d;
}
__device__ __forceinline__ float f2hadd(unsigned long long a) {
    float lo, hi;
    asm("mov.b64 {%0, %1}, %2;" : "=f"(lo), "=f"(hi) : "l"(a));
    return lo + hi;
}

// ---- cp.async (LDGSTS) helpers ----
__device__ __forceinline__ void cp16(uint32_t dst, const void* src) {
    asm volatile("cp.async.ca.shared.global [%0], [%1], 16;" :: "r"(dst), "l"(src));
}
__device__ __forceinline__ void cp_commit() { asm volatile("cp.async.commit_group;"); }
template <int N>
__device__ __forceinline__ void cp_wait() { asm volatile("cp.async.wait_group %0;" :: "n"(N)); }
__device__ __forceinline__ uint32_t sptr(const void* p) {
    return (uint32_t)__cvta_generic_to_shared(p);
}

// One fused pass: recompute u_hat tile-by-tile (double-buffered cp.async
// staging), route, accumulate s in regs, flush with atomics; LAST block
// performs squash (fused epilogue).
// Thread layout: lane = d (16), grp = tid>>4 (32 groups); each thread
// covers batches b0=grp and b1=grp+32, so every W value staged in shared
// is consumed for 2 batches (halves LDS traffic vs 1-batch/thread).
template <int ITER>
__global__ void __launch_bounds__(NTHR, 2)
pass_kernel(const float* __restrict__ xg, const float* __restrict__ Wg,
            float* __restrict__ out)
{
    __shared__ float4 shW[2][ITILE * NO * 32];  // 2 x 10 KB, (j,o): idx = e4*16 + d
    __shared__ float4 shx[2][ITILE * NB * 2];   // 2 x 4 KB

    const int tid  = threadIdx.x;
    const int lane = tid & 15;   // d
    const int grp  = tid >> 4;   // 0..31
    const int b0 = grp, b1 = grp + 32;

    const bool s8 = (lane & 8) != 0;
    const bool s4 = (lane & 4) != 0;
    const bool s2 = (lane & 2) != 0;
    const bool s1 = (lane & 1) != 0;
    // lane g holds a[o(g)]; valid (non-duplicate) lanes for softmax denom:
    const bool validLane = (!s1) || (!s2 && !s4);

    float vr0[NO], vr1[NO];
    if (ITER >= 1) {
        const float* vin = (ITER == 1) ? g_v : g_vsum;
        #pragma unroll
        for (int o = 0; o < NO; o++) {
            vr0[o] = vin[(b0 * NO + o) * ND + lane];
            vr1[o] = vin[(b1 * NO + o) * ND + lane];
        }
    }

    unsigned long long accp0[NO], accp1[NO];  // ITER 0: packed accumulators
    float acc0[NO], acc1[NO];
    #pragma unroll
    for (int o = 0; o < NO; o++) {
        accp0[o] = 0ull; accp1[o] = 0ull; acc0[o] = 0.f; acc1[o] = 0.f;
    }

    const float4* Wf4 = (const float4*)Wg;
    const float4* xf4 = (const float4*)xg;

    // staging: 896 float4 items per stage, 512 threads -> <=2 cp16 each
    auto stage_load = [&](int buf, int st) {
        const int i0 = st * ITILE;
        #pragma unroll
        for (int t = tid; t < ITILE * NO * 32 + ITILE * NB * 2; t += NTHR) {
            if (t < ITILE * NO * 32) {             // 640 W float4s
                int j  = t / (NO * 32);
                int r  = t - j * (NO * 32);
                int o  = r >> 5;
                int qg = r & 31;                       // global: d*2 + e4
                int qs = ((qg & 1) << 4) | (qg >> 1);  // shared: e4*16 + d
                cp16(sptr(&shW[buf][(j * NO + o) * 32 + qs]),
                     &Wf4[(o * NI + i0 + j) * 32 + qg]);
            } else {                               // 256 x float4s
                int v = t - ITILE * NO * 32;
                int j = v >> 7;
                int r = v & 127;
                int bb = r >> 1;
                int q  = r & 1;
                cp16(sptr(&shx[buf][(j * NB + bb) * 2 + q]),
                     &xf4[((bb * NI + i0 + j) << 1) + q]);
            }
        }
    };

    // prologue: stage this block's first tile
    stage_load(0, blockIdx.x);
    cp_commit();

    int parity = 0;
    for (int st = blockIdx.x; st < NSTAGES; st += NBLK) {
        const int nxt = st + NBLK;
        if (nxt < NSTAGES) {
            stage_load(parity ^ 1, nxt);
            cp_commit();
            cp_wait<1>();           // current stage's group complete
        } else {
            cp_wait<0>();
        }
        __syncthreads();

        const ulonglong2* shWc = reinterpret_cast<const ulonglong2*>(shW[parity]);
        const ulonglong2* shxc = reinterpret_cast<const ulonglong2*>(shx[parity]);

        #pragma unroll
        for (int j = 0; j < ITILE; j++) {
            ulonglong2 xa0 = shxc[(j * NB + b0) * 2 + 0];  // (e0,e1),(e2,e3)
            ulonglong2 xb0 = shxc[(j * NB + b0) * 2 + 1];  // (e4,e5),(e6,e7)
            ulonglong2 xa1 = shxc[(j * NB + b1) * 2 + 0];
            ulonglong2 xb1 = shxc[(j * NB + b1) * 2 + 1];

            if (ITER == 0) {
                #pragma unroll
                for (int o = 0; o < NO; o++) {
                    ulonglong2 wa = shWc[(j * NO + o) * 32 + lane];       // e0..3
                    ulonglong2 wb = shWc[(j * NO + o) * 32 + 16 + lane];  // e4..7
                    accp0[o] = f2fma(wa.x, xa0.x, accp0[o]);
                    accp0[o] = f2fma(wa.y, xa0.y, accp0[o]);
                    accp0[o] = f2fma(wb.x, xb0.x, accp0[o]);
                    accp0[o] = f2fma(wb.y, xb0.y, accp0[o]);
                    accp1[o] = f2fma(wa.x, xa1.x, accp1[o]);
                    accp1[o] = f2fma(wa.y, xa1.y, accp1[o]);
                    accp1[o] = f2fma(wb.x, xb1.x, accp1[o]);
                    accp1[o] = f2fma(wb.y, xb1.y, accp1[o]);
                }
            } else {
                float u0[NO], u1[NO];
                #pragma unroll
                for (int o = 0; o < NO; o++) {
                    ulonglong2 wa = shWc[(j * NO + o) * 32 + lane];
                    ulonglong2 wb = shWc[(j * NO + o) * 32 + 16 + lane];
                    unsigned long long t0 = f2mul(wa.x, xa0.x);
                    t0 = f2fma(wa.y, xa0.y, t0);
                    t0 = f2fma(wb.x, xb0.x, t0);
                    t0 = f2fma(wb.y, xb0.y, t0);
                    u0[o] = f2hadd(t0);
                    unsigned long long t1 = f2mul(wa.x, xa1.x);
                    t1 = f2fma(wa.y, xa1.y, t1);
                    t1 = f2fma(wb.x, xb1.x, t1);
                    t1 = f2fma(wb.y, xb1.y, t1);
                    u1[o] = f2hadd(t1);
                }

                #pragma unroll
                for (int bb = 0; bb < 2; bb++) {
                    const float* u  = bb ? u1 : u0;
                    const float* vr = bb ? vr1 : vr0;
                    float* acc = bb ? acc1 : acc0;

                    // pairing-tree reduction of p[o]=u[o]*vr[o] over 16 d-lanes
                    float p[NO];
                    #pragma unroll
                    for (int o = 0; o < NO; o++) p[o] = u[o] * vr[o];

                    float q[5];
                    #pragma unroll
                    for (int k = 0; k < 5; k++) {
                        float keep = s8 ? p[2 * k + 1] : p[2 * k];
                        float send = s8 ? p[2 * k] : p[2 * k + 1];
                        q[k] = keep + __shfl_xor_sync(0xffffffffu, send, 8, 16);
                    }
                    float r0, r1, r2;
                    {
                        float keep = s4 ? q[1] : q[0];
                        float send = s4 ? q[0] : q[1];
                        r0 = keep + __shfl_xor_sync(0xffffffffu, send, 4, 16);
                    }
                    {
                        float keep = s4 ? q[3] : q[2];
                        float send = s4 ? q[2] : q[3];
                        r1 = keep + __shfl_xor_sync(0xffffffffu, send, 4, 16);
                    }
                    r2 = q[4] + __shfl_xor_sync(0xffffffffu, q[4], 4, 16);
                    float t0, t1;
                    {
                        float keep = s2 ? r1 : r0;
                        float send = s2 ? r0 : r1;
                        t0 = keep + __shfl_xor_sync(0xffffffffu, send, 2, 16);
                    }
                    t1 = r2 + __shfl_xor_sync(0xffffffffu, r2, 2, 16);
                    float a;
                    {
                        float keep = s1 ? t1 : t0;
                        float send = s1 ? t0 : t1;
                        a = keep + __shfl_xor_sync(0xffffffffu, send, 1, 16);
                    }

                    // distributed softmax (logits tiny -> no max subtraction)
                    float e = __expf(a);
                    float m = validLane ? e : 0.f;
                    m += __shfl_xor_sync(0xffffffffu, m, 8, 16);
                    m += __shfl_xor_sync(0xffffffffu, m, 4, 16);
                    m += __shfl_xor_sync(0xffffffffu, m, 2, 16);
                    m += __shfl_xor_sync(0xffffffffu, m, 1, 16);
                    float c_self = __fdividef(e, m);

                    // broadcast c[o] from its owner lane, accumulate
                    // o -> lane: {0,8,4,12,2,10,6,14,1,9}
                    acc[0] = fmaf(__shfl_sync(0xffffffffu, c_self, 0, 16),  u[0], acc[0]);
                    acc[1] = fmaf(__shfl_sync(0xffffffffu, c_self, 8, 16),  u[1], acc[1]);
                    acc[2] = fmaf(__shfl_sync(0xffffffffu, c_self, 4, 16),  u[2], acc[2]);
                    acc[3] = fmaf(__shfl_sync(0xffffffffu, c_self, 12, 16), u[3], acc[3]);
                    acc[4] = fmaf(__shfl_sync(0xffffffffu, c_self, 2, 16),  u[4], acc[4]);
                    acc[5] = fmaf(__shfl_sync(0xffffffffu, c_self, 10, 16), u[5], acc[5]);
                    acc[6] = fmaf(__shfl_sync(0xffffffffu, c_self, 6, 16),  u[6], acc[6]);
                    acc[7] = fmaf(__shfl_sync(0xffffffffu, c_self, 14, 16), u[7], acc[7]);
                    acc[8] = fmaf(__shfl_sync(0xffffffffu, c_self, 1, 16),  u[8], acc[8]);
                    acc[9] = fmaf(__shfl_sync(0xffffffffu, c_self, 9, 16),  u[9], acc[9]);
                }
            }
        }

        __syncthreads();  // compute done before next iter overwrites this buffer
        parity ^= 1;
    }

    if (ITER == 0) {
        #pragma unroll
        for (int o = 0; o < NO; o++) {
            acc0[o] = f2hadd(accp0[o]);
            acc1[o] = f2hadd(accp1[o]);
        }
    }
    #pragma unroll
    for (int o = 0; o < NO; o++) {
        atomicAdd(&g_s[(b0 * NO + o) * ND + lane], acc0[o]);
        atomicAdd(&g_s[(b1 * NO + o) * ND + lane], acc1[o]);
    }

    // ---- fused squash: last block to finish does the epilogue ----
    __threadfence();
    __shared__ unsigned int lastFlag;
    if (tid == 0)
        lastFlag = (atomicAdd(&g_ticket, 1u) == (unsigned)(gridDim.x - 1)) ? 1u : 0u;
    __syncthreads();
    if (!lastFlag) return;
    __threadfence();  // acquire: all other blocks' atomics are visible

    const float prescale = (ITER == 0) ? 0.1f : 1.0f;
    #pragma unroll
    for (int k = 0; k < (NB * NO * ND) / NTHR; k++) {
        int idx = k * NTHR + tid;            // idx & 15 == lane (NTHR % 16 == 0)
        float val = g_s[idx] * prescale;
        g_s[idx] = 0.f;
        float n2 = val * val;
        n2 += __shfl_xor_sync(0xffffffffu, n2, 8, 16);
        n2 += __shfl_xor_sync(0xffffffffu, n2, 4, 16);
        n2 += __shfl_xor_sync(0xffffffffu, n2, 2, 16);
        n2 += __shfl_xor_sync(0xffffffffu, n2, 1, 16);
        float norm  = sqrtf(n2);
        float scale = n2 / ((1.f + n2) * (norm + 1e-8f));
        float v = scale * val;
        if (ITER == 0)      { g_v[idx] = v; g_vsum[idx] = v; }
        else if (ITER == 1) { g_v[idx] = v; g_vsum[idx] += v; }
        else                { out[idx] = v; }
    }
    if (tid == 0) g_ticket = 0;  // reset for next pass / next graph replay
}

extern "C" void kernel_launch(void* const* d_in, const int* in_sizes, int n_in,
                              void* d_out, int out_size)
{
    const float* x = (const float*)d_in[0];  // [64, 8000, 8]
    const float* W = (const float*)d_in[1];  // [10, 8000, 16, 8]
    float* out = (float*)d_out;              // [64, 10, 16]

    pass_kernel<0><<<NBLK, NTHR>>>(x, W, out);  // uniform c=0.1 (in prescale)
    pass_kernel<1><<<NBLK, NTHR>>>(x, W, out);  // c = softmax_o(u.v0)
    pass_kernel<2><<<NBLK, NTHR>>>(x, W, out);  // c = softmax_o(u.(v0+v1))
}

// round 6
// speedup vs baseline: 1.1693x; 1.0017x over previous
#include <cuda_runtime.h>
#include <cstdint>

#define NB 64
#define NO 10
#define NI 8000
#define ND 16
#define NE 8

#define ITILE 2
#define NTHR 512
#define NSTAGES (NI / ITILE)   // 4000 stages of 2 i's
#define NBLK 296               // 2 blocks/SM resident (persistent)

// Scratch (no allocation allowed). g_s zeroed by the fused squash each pass,
// g_ticket reset by the last block -> graph replays are deterministic.
__device__ float g_s[NB * NO * ND] = {};
__device__ float g_v[NB * NO * ND] = {};
__device__ float g_vsum[NB * NO * ND] = {};
__device__ unsigned int g_ticket = 0;

// ---- f32x2 packed math (sm_10x; ptxas won't auto-fuse, must be PTX) ----
__device__ __forceinline__ unsigned long long f2mul(unsigned long long a, unsigned long long b) {
    unsigned long long d;
    asm("mul.rn.f32x2 %0, %1, %2;" : "=l"(d) : "l"(a), "l"(b));
    return d;
}
__device__ __forceinline__ unsigned long long f2fma(unsigned long long a, unsigned long long b, unsigned long long c) {
    unsigned long long d;
    asm("fma.rn.f32x2 %0, %1, %2, %3;" : "=l"(d) : "l"(a), "l"(b), "l"(c));
    return d;
}
__device__ __forceinline__ float f2hadd(unsigned long long a) {
    float lo, hi;
    asm("mov.b64 {%0, %1}, %2;" : "=f"(lo), "=f"(hi) : "l"(a));
    return lo + hi;
}

// ---- cp.async (LDGSTS) helpers ----
__device__ __forceinline__ void cp16(uint32_t dst, const void* src) {
    asm volatile("cp.async.ca.shared.global [%0], [%1], 16;" :: "r"(dst), "l"(src));
}
__device__ __forceinline__ void cp_commit() { asm volatile("cp.async.commit_group;"); }
template <int N>
__device__ __forceinline__ void cp_wait() { asm volatile("cp.async.wait_group %0;" :: "n"(N)); }
__device__ __forceinline__ uint32_t sptr(const void* p) {
    return (uint32_t)__cvta_generic_to_shared(p);
}

// One fused pass: recompute u_hat tile-by-tile (double-buffered cp.async
// staging), route, accumulate s in regs, flush with atomics; LAST block
// performs squash (fused epilogue).
// Thread layout: lane = d (16), grp = tid>>4 (32 groups); each thread
// covers batches b0=grp and b1=grp+32, so every W value staged in shared
// is consumed for 2 batches (halves LDS traffic vs 1-batch/thread).
template <int ITER>
__global__ void __launch_bounds__(NTHR, 2)
pass_kernel(const float* __restrict__ xg, const float* __restrict__ Wg,
            float* __restrict__ out)
{
    __shared__ float4 shW[2][ITILE * NO * 32];  // 2 x 10 KB, (j,o): idx = e4*16 + d
    __shared__ float4 shx[2][ITILE * NB * 2];   // 2 x 4 KB

    const int tid  = threadIdx.x;
    const int lane = tid & 15;   // d
    const int grp  = tid >> 4;   // 0..31
    const int b0 = grp, b1 = grp + 32;

    const bool s8 = (lane & 8) != 0;
    const bool s4 = (lane & 4) != 0;
    const bool s2 = (lane & 2) != 0;
    const bool s1 = (lane & 1) != 0;
    // lane g holds a[o(g)]; valid (non-duplicate) lanes for softmax denom:
    const bool validLane = (!s1) || (!s2 && !s4);

    float vr0[NO], vr1[NO];
    if (ITER >= 1) {
        const float* vin = (ITER == 1) ? g_v : g_vsum;
        #pragma unroll
        for (int o = 0; o < NO; o++) {
            vr0[o] = vin[(b0 * NO + o) * ND + lane];
            vr1[o] = vin[(b1 * NO + o) * ND + lane];
        }
    }

    unsigned long long accp0[NO], accp1[NO];  // ITER 0: packed accumulators
    float acc0[NO], acc1[NO];
    #pragma unroll
    for (int o = 0; o < NO; o++) {
        accp0[o] = 0ull; accp1[o] = 0ull; acc0[o] = 0.f; acc1[o] = 0.f;
    }

    const float4* Wf4 = (const float4*)Wg;
    const float4* xf4 = (const float4*)xg;

    // staging: 896 float4 items per stage, 512 threads -> <=2 cp16 each
    auto stage_load = [&](int buf, int st) {
        const int i0 = st * ITILE;
        #pragma unroll
        for (int t = tid; t < ITILE * NO * 32 + ITILE * NB * 2; t += NTHR) {
            if (t < ITILE * NO * 32) {             // 640 W float4s
                int j  = t / (NO * 32);
                int r  = t - j * (NO * 32);
                int o  = r >> 5;
                int qg = r & 31;                       // global: d*2 + e4
                int qs = ((qg & 1) << 4) | (qg >> 1);  // shared: e4*16 + d
                cp16(sptr(&shW[buf][(j * NO + o) * 32 + qs]),
                     &Wf4[(o * NI + i0 + j) * 32 + qg]);
            } else {                               // 256 x float4s
                int v = t - ITILE * NO * 32;
                int j = v >> 7;
                int r = v & 127;
                int bb = r >> 1;
                int q  = r & 1;
                cp16(sptr(&shx[buf][(j * NB + bb) * 2 + q]),
                     &xf4[((bb * NI + i0 + j) << 1) + q]);
            }
        }
    };

    // prologue: stage this block's first tile
    stage_load(0, blockIdx.x);
    cp_commit();

    int parity = 0;
    for (int st = blockIdx.x; st < NSTAGES; st += NBLK) {
        const int nxt = st + NBLK;
        if (nxt < NSTAGES) {
            stage_load(parity ^ 1, nxt);
            cp_commit();
            cp_wait<1>();           // current stage's group complete
        } else {
            cp_wait<0>();
        }
        __syncthreads();

        const ulonglong2* shWc = reinterpret_cast<const ulonglong2*>(shW[parity]);
        const ulonglong2* shxc = reinterpret_cast<const ulonglong2*>(shx[parity]);

        #pragma unroll
        for (int j = 0; j < ITILE; j++) {
            ulonglong2 xa0 = shxc[(j * NB + b0) * 2 + 0];  // (e0,e1),(e2,e3)
            ulonglong2 xb0 = shxc[(j * NB + b0) * 2 + 1];  // (e4,e5),(e6,e7)
            ulonglong2 xa1 = shxc[(j * NB + b1) * 2 + 0];
            ulonglong2 xb1 = shxc[(j * NB + b1) * 2 + 1];

            if (ITER == 0) {
                #pragma unroll
                for (int o = 0; o < NO; o++) {
                    ulonglong2 wa = shWc[(j * NO + o) * 32 + lane];       // e0..3
                    ulonglong2 wb = shWc[(j * NO + o) * 32 + 16 + lane];  // e4..7
                    accp0[o] = f2fma(wa.x, xa0.x, accp0[o]);
                    accp0[o] = f2fma(wa.y, xa0.y, accp0[o]);
                    accp0[o] = f2fma(wb.x, xb0.x, accp0[o]);
                    accp0[o] = f2fma(wb.y, xb0.y, accp0[o]);
                    accp1[o] = f2fma(wa.x, xa1.x, accp1[o]);
                    accp1[o] = f2fma(wa.y, xa1.y, accp1[o]);
                    accp1[o] = f2fma(wb.x, xb1.x, accp1[o]);
                    accp1[o] = f2fma(wb.y, xb1.y, accp1[o]);
                }
            } else {
                float u0[NO], u1[NO];
                #pragma unroll
                for (int o = 0; o < NO; o++) {
                    ulonglong2 wa = shWc[(j * NO + o) * 32 + lane];
                    ulonglong2 wb = shWc[(j * NO + o) * 32 + 16 + lane];
                    unsigned long long t0 = f2mul(wa.x, xa0.x);
                    t0 = f2fma(wa.y, xa0.y, t0);
                    t0 = f2fma(wb.x, xb0.x, t0);
                    t0 = f2fma(wb.y, xb0.y, t0);
                    u0[o] = f2hadd(t0);
                    unsigned long long t1 = f2mul(wa.x, xa1.x);
                    t1 = f2fma(wa.y, xa1.y, t1);
                    t1 = f2fma(wb.x, xb1.x, t1);
                    t1 = f2fma(wb.y, xb1.y, t1);
                    u1[o] = f2hadd(t1);
                }

                #pragma unroll
                for (int bb = 0; bb < 2; bb++) {
                    const float* u  = bb ? u1 : u0;
                    const float* vr = bb ? vr1 : vr0;
                    float* acc = bb ? acc1 : acc0;

                    // pairing-tree reduction of p[o]=u[o]*vr[o] over 16 d-lanes
                    float p[NO];
                    #pragma unroll
                    for (int o = 0; o < NO; o++) p[o] = u[o] * vr[o];

                    float q[5];
                    #pragma unroll
                    for (int k = 0; k < 5; k++) {
                        float keep = s8 ? p[2 * k + 1] : p[2 * k];
                        float send = s8 ? p[2 * k] : p[2 * k + 1];
                        q[k] = keep + __shfl_xor_sync(0xffffffffu, send, 8, 16);
                    }
                    float r0, r1, r2;
                    {
                        float keep = s4 ? q[1] : q[0];
                        float send = s4 ? q[0] : q[1];
                        r0 = keep + __shfl_xor_sync(0xffffffffu, send, 4, 16);
                    }
                    {
                        float keep = s4 ? q[3] : q[2];
                        float send = s4 ? q[2] : q[3];
                        r1 = keep + __shfl_xor_sync(0xffffffffu, send, 4, 16);
                    }
                    r2 = q[4] + __shfl_xor_sync(0xffffffffu, q[4], 4, 16);
                    float t0, t1;
                    {
                        float keep = s2 ? r1 : r0;
                        float send = s2 ? r0 : r1;
                        t0 = keep + __shfl_xor_sync(0xffffffffu, send, 2, 16);
                    }
                    t1 = r2 + __shfl_xor_sync(0xffffffffu, r2, 2, 16);
                    float a;
                    {
                        float keep = s1 ? t1 : t0;
                        float send = s1 ? t0 : t1;
                        a = keep + __shfl_xor_sync(0xffffffffu, send, 1, 16);
                    }

                    // distributed softmax (logits tiny -> no max subtraction)
                    float e = __expf(a);
                    float m = validLane ? e : 0.f;
                    m += __shfl_xor_sync(0xffffffffu, m, 8, 16);
                    m += __shfl_xor_sync(0xffffffffu, m, 4, 16);
                    m += __shfl_xor_sync(0xffffffffu, m, 2, 16);
                    m += __shfl_xor_sync(0xffffffffu, m, 1, 16);
                    float c_self = __fdividef(e, m);

                    // broadcast c[o] from its owner lane, accumulate
                    // o -> lane: {0,8,4,12,2,10,6,14,1,9}
                    acc[0] = fmaf(__shfl_sync(0xffffffffu, c_self, 0, 16),  u[0], acc[0]);
                    acc[1] = fmaf(__shfl_sync(0xffffffffu, c_self, 8, 16),  u[1], acc[1]);
                    acc[2] = fmaf(__shfl_sync(0xffffffffu, c_self, 4, 16),  u[2], acc[2]);
                    acc[3] = fmaf(__shfl_sync(0xffffffffu, c_self, 12, 16), u[3], acc[3]);
                    acc[4] = fmaf(__shfl_sync(0xffffffffu, c_self, 2, 16),  u[4], acc[4]);
                    acc[5] = fmaf(__shfl_sync(0xffffffffu, c_self, 10, 16), u[5], acc[5]);
                    acc[6] = fmaf(__shfl_sync(0xffffffffu, c_self, 6, 16),  u[6], acc[6]);
                    acc[7] = fmaf(__shfl_sync(0xffffffffu, c_self, 14, 16), u[7], acc[7]);
                    acc[8] = fmaf(__shfl_sync(0xffffffffu, c_self, 1, 16),  u[8], acc[8]);
                    acc[9] = fmaf(__shfl_sync(0xffffffffu, c_self, 9, 16),  u[9], acc[9]);
                }
            }
        }

        __syncthreads();  // compute done before next iter overwrites this buffer
        parity ^= 1;
    }

    if (ITER == 0) {
        #pragma unroll
        for (int o = 0; o < NO; o++) {
            acc0[o] = f2hadd(accp0[o]);
            acc1[o] = f2hadd(accp1[o]);
        }
    }
    #pragma unroll
    for (int o = 0; o < NO; o++) {
        atomicAdd(&g_s[(b0 * NO + o) * ND + lane], acc0[o]);
        atomicAdd(&g_s[(b1 * NO + o) * ND + lane], acc1[o]);
    }

    // ---- fused squash: last block to finish does the epilogue ----
    __threadfence();
    __shared__ unsigned int lastFlag;
    if (tid == 0)
        lastFlag = (atomicAdd(&g_ticket, 1u) == (unsigned)(gridDim.x - 1)) ? 1u : 0u;
    __syncthreads();
    if (!lastFlag) return;
    __threadfence();  // acquire: all other blocks' atomics are visible

    const float prescale = (ITER == 0) ? 0.1f : 1.0f;
    #pragma unroll
    for (int k = 0; k < (NB * NO * ND) / NTHR; k++) {
        int idx = k * NTHR + tid;            // idx & 15 == lane (NTHR % 16 == 0)
        float val = g_s[idx] * prescale;
        g_s[idx] = 0.f;
        float n2 = val * val;
        n2 += __shfl_xor_sync(0xffffffffu, n2, 8, 16);
        n2 += __shfl_xor_sync(0xffffffffu, n2, 4, 16);
        n2 += __shfl_xor_sync(0xffffffffu, n2, 2, 16);
        n2 += __shfl_xor_sync(0xffffffffu, n2, 1, 16);
        float norm  = sqrtf(n2);
        float scale = n2 / ((1.f + n2) * (norm + 1e-8f));
        float v = scale * val;
        if (ITER == 0)      { g_v[idx] = v; g_vsum[idx] = v; }
        else if (ITER == 1) { g_v[idx] = v; g_vsum[idx] += v; }
        else                { out[idx] = v; }
    }
    if (tid == 0) g_ticket = 0;  // reset for next pass / next graph replay
}

extern "C" void kernel_launch(void* const* d_in, const int* in_sizes, int n_in,
                              void* d_out, int out_size)
{
    const float* x = (const float*)d_in[0];  // [64, 8000, 8]
    const float* W = (const float*)d_in[1];  // [10, 8000, 16, 8]
    float* out = (float*)d_out;              // [64, 10, 16]

    pass_kernel<0><<<NBLK, NTHR>>>(x, W, out);  // uniform c=0.1 (in prescale)
    pass_kernel<1><<<NBLK, NTHR>>>(x, W, out);  // c = softmax_o(u.v0)
    pass_kernel<2><<<NBLK, NTHR>>>(x, W, out);  // c = softmax_o(u.(v0+v1))
}